// round 9
// baseline (speedup 1.0000x reference)
#include <cuda_runtime.h>

// Bundle-adjustment reprojection residual.
//   d_in[0] observes  float32 [N_OBS, 2]
//   d_in[1] K         float32 [3, 3]
//   d_in[2] poses     float32 [N_CAM, 7]   (t[3], qv[3], qw)
//   d_in[3] points    float32 [N_PTS, 3]
//   d_in[4] cidx      int32   [N_OBS]
//   d_in[5] pidx      int32   [N_OBS]
// Output: float32 [N_OBS*2]  residual = proj - observe
//
// R7 strategy:
//  - vectorized prologue repacks points into float4 (one LDG.128 per gather)
//  - pose table in smem as TWO float4 arrays (64KB total) -> 3 blocks/SM, 75% occ
//  - 512-thread blocks, 4 obs per thread, fully vectorized streams

#define THREADS 512
#define N_PTS_MAX 500032

__device__ float4 g_points4[N_PTS_MAX];

// Each thread repacks 4 points: reads 3 float4 (12 floats), writes 4 float4.
__global__ __launch_bounds__(256) void repack_points_kernel(
    const float4* __restrict__ points4, const float* __restrict__ points,
    int n_quads, int n_pts)
{
    int i = blockIdx.x * blockDim.x + threadIdx.x;
    if (i < n_quads) {
        float4 v0 = __ldg(&points4[3 * i]);
        float4 v1 = __ldg(&points4[3 * i + 1]);
        float4 v2 = __ldg(&points4[3 * i + 2]);
        g_points4[4 * i + 0] = make_float4(v0.x, v0.y, v0.z, 0.0f);
        g_points4[4 * i + 1] = make_float4(v0.w, v1.x, v1.y, 0.0f);
        g_points4[4 * i + 2] = make_float4(v1.z, v1.w, v2.x, 0.0f);
        g_points4[4 * i + 3] = make_float4(v2.y, v2.z, v2.w, 0.0f);
    }
    // tail (n_pts % 4) handled by the first few threads of block 0
    int rem_base = n_quads * 4;
    int r = rem_base + i;
    if (blockIdx.x == 0 && r < n_pts) {
        const float* p = points + (size_t)r * 3;
        g_points4[r] = make_float4(__ldg(p), __ldg(p + 1), __ldg(p + 2), 0.0f);
    }
}

__global__ __launch_bounds__(THREADS, 3) void residual_kernel(
    const float4* __restrict__ obs4,
    const float* __restrict__ K,
    const float* __restrict__ poses,
    const int4* __restrict__ cidx4,
    const int4* __restrict__ pidx4,
    const int* __restrict__ cidx,
    const int* __restrict__ pidx,
    const float2* __restrict__ obs2,
    float4* __restrict__ out4,
    float2* __restrict__ out2,
    int n_obs, int n_cam)
{
    extern __shared__ float4 psm[];   // [n_cam] a-rows then [n_cam] b-rows
    float4* pa_t = psm;               // tx ty tz qx
    float4* pb_t = psm + n_cam;       // qy qz qw pad

    const int tid = threadIdx.x;

    // Stage poses: 7 floats/cam -> split float4 tables.
    {
        float* a_f = (float*)pa_t;
        float* b_f = (float*)pb_t;
        const int n_pose_f = n_cam * 7;
        for (int idx = tid; idx < n_pose_f; idx += THREADS) {
            int c = idx / 7;
            int k = idx - c * 7;
            float v = __ldg(&poses[idx]);
            if (k < 4) a_f[c * 4 + k] = v;
            else       b_f[c * 4 + (k - 4)] = v;
        }
        // zero pads (not strictly needed; qw pad unused)
    }
    __syncthreads();

    const float fx = __ldg(&K[0]);
    const float cxx = __ldg(&K[2]);
    const float fy = __ldg(&K[4]);
    const float cyy = __ldg(&K[5]);

    const int n_quads = n_obs >> 2;
    const int gsz = gridDim.x * THREADS;

    for (int q = blockIdx.x * THREADS + tid; q < n_quads; q += gsz) {
        int4 c4 = __ldg(&cidx4[q]);
        int4 p4 = __ldg(&pidx4[q]);

        float4 ob0 = __ldg(&obs4[2 * q]);
        float4 ob1 = __ldg(&obs4[2 * q + 1]);

        int pis[4] = {p4.x, p4.y, p4.z, p4.w};
        int cis[4] = {c4.x, c4.y, c4.z, c4.w};

        // One LDG.128 per point (all 4 issued up front for MLP)
        float4 pt[4];
        #pragma unroll
        for (int j = 0; j < 4; j++)
            pt[j] = __ldg(&g_points4[pis[j]]);

        // Two LDS.128 per pose
        float4 pa[4], pb[4];
        #pragma unroll
        for (int j = 0; j < 4; j++) {
            pa[j] = pa_t[cis[j]];
            pb[j] = pb_t[cis[j]];
        }

        float res[8];
        float obx[4] = {ob0.x, ob0.z, ob1.x, ob1.z};
        float oby[4] = {ob0.y, ob0.w, ob1.y, ob1.w};

        #pragma unroll
        for (int j = 0; j < 4; j++) {
            float tx = pa[j].x, ty = pa[j].y, tz = pa[j].z;
            float qx = pa[j].w, qy = pb[j].x, qz = pb[j].y, qw = pb[j].z;
            float X = pt[j].x, Y = pt[j].y, Z = pt[j].z;

            float uvx = qy * Z - qz * Y;
            float uvy = qz * X - qx * Z;
            float uvz = qx * Y - qy * X;
            float wx = fmaf(qw, X, uvx);
            float wy = fmaf(qw, Y, uvy);
            float wz = fmaf(qw, Z, uvz);
            float c2x = qy * wz - qz * wy;
            float c2y = qz * wx - qx * wz;
            float c2z = qx * wy - qy * wx;
            float Xc = fmaf(2.0f, c2x, X) + tx;
            float Yc = fmaf(2.0f, c2y, Y) + ty;
            float Zc = fmaf(2.0f, c2z, Z) + tz;

            float invz = __fdividef(1.0f, Zc);
            res[2 * j + 0] = fmaf(fx * Xc, invz, cxx) - obx[j];
            res[2 * j + 1] = fmaf(fy * Yc, invz, cyy) - oby[j];
        }

        out4[2 * q]     = make_float4(res[0], res[1], res[2], res[3]);
        out4[2 * q + 1] = make_float4(res[4], res[5], res[6], res[7]);
    }

    // ---- tail: n_obs % 4 leftovers (block 0 only) ----
    const int rem_base = n_quads << 2;
    if (blockIdx.x == 0) {
        for (int i = rem_base + tid; i < n_obs; i += THREADS) {
            int ci = __ldg(&cidx[i]);
            int pi = __ldg(&pidx[i]);
            float4 a = pa_t[ci];
            float4 b = pb_t[ci];
            float tx = a.x, ty = a.y, tz = a.z;
            float qx = a.w, qy = b.x, qz = b.y, qw = b.z;
            float4 p = __ldg(&g_points4[pi]);
            float X = p.x, Y = p.y, Z = p.z;

            float uvx = qy * Z - qz * Y;
            float uvy = qz * X - qx * Z;
            float uvz = qx * Y - qy * X;
            float wx = fmaf(qw, X, uvx);
            float wy = fmaf(qw, Y, uvy);
            float wz = fmaf(qw, Z, uvz);
            float c2x = qy * wz - qz * wy;
            float c2y = qz * wx - qx * wz;
            float c2z = qx * wy - qy * wx;
            float Xc = fmaf(2.0f, c2x, X) + tx;
            float Yc = fmaf(2.0f, c2y, Y) + ty;
            float Zc = fmaf(2.0f, c2z, Z) + tz;
            float invz = __fdividef(1.0f, Zc);
            float2 ob = __ldg(&obs2[i]);
            float2 r;
            r.x = fmaf(fx * Xc, invz, cxx) - ob.x;
            r.y = fmaf(fy * Yc, invz, cyy) - ob.y;
            out2[i] = r;
        }
    }
}

extern "C" void kernel_launch(void* const* d_in, const int* in_sizes, int n_in,
                              void* d_out, int out_size) {
    const float* observes = (const float*)d_in[0];
    const float* K        = (const float*)d_in[1];
    const float* poses    = (const float*)d_in[2];
    const float* points   = (const float*)d_in[3];
    const int* cidx       = (const int*)d_in[4];
    const int* pidx       = (const int*)d_in[5];

    int n_obs = in_sizes[0] / 2;
    int n_cam = in_sizes[2] / 7;
    int n_pts = in_sizes[3] / 3;
    if (n_pts > N_PTS_MAX) n_pts = N_PTS_MAX;

    int smem = n_cam * 2 * sizeof(float4);  // 64000 B for n_cam=2000

    cudaFuncSetAttribute(residual_kernel,
                         cudaFuncAttributeMaxDynamicSharedMemorySize, smem);

    int pq = n_pts / 4;
    int pblocks = (pq + 255) / 256;
    if (pblocks < 1) pblocks = 1;
    repack_points_kernel<<<pblocks, 256>>>((const float4*)points, points, pq, n_pts);

    int blocks = 148 * 3;  // 3 blocks/SM (64KB smem each), 75% occ
    residual_kernel<<<blocks, THREADS, smem>>>(
        (const float4*)observes, K, poses,
        (const int4*)cidx, (const int4*)pidx,
        cidx, pidx, (const float2*)observes,
        (float4*)d_out, (float2*)d_out,
        n_obs, n_cam);
}

// round 10
// speedup vs baseline: 1.2317x; 1.2317x over previous
#include <cuda_runtime.h>

// Bundle-adjustment reprojection residual.
//   d_in[0] observes  float32 [N_OBS, 2]
//   d_in[1] K         float32 [3, 3]
//   d_in[2] poses     float32 [N_CAM, 7]   (t[3], qv[3], qw)
//   d_in[3] points    float32 [N_PTS, 3]
//   d_in[4] cidx      int32   [N_OBS]
//   d_in[5] pidx      int32   [N_OBS]
// Output: float32 [N_OBS*2]  residual = proj - observe
//
// R10 strategy:
//  - prologue repacks points into float4 (one LDG.128 per gather)
//  - pose table in smem as two float4 arrays (64KB)
//  - 384-thread blocks, 2/SM (reg cap ~85): software-pipelined grid-stride
//    loop double-buffers indices + point gathers so point-LDG latency
//    overlaps with the previous iteration's compute.

#define THREADS 384
#define N_PTS_MAX 500032

__device__ float4 g_points4[N_PTS_MAX];

// Each thread repacks 4 points: reads 3 float4 (12 floats), writes 4 float4.
__global__ __launch_bounds__(256) void repack_points_kernel(
    const float4* __restrict__ points4, const float* __restrict__ points,
    int n_quads, int n_pts)
{
    int i = blockIdx.x * blockDim.x + threadIdx.x;
    if (i < n_quads) {
        float4 v0 = __ldg(&points4[3 * i]);
        float4 v1 = __ldg(&points4[3 * i + 1]);
        float4 v2 = __ldg(&points4[3 * i + 2]);
        g_points4[4 * i + 0] = make_float4(v0.x, v0.y, v0.z, 0.0f);
        g_points4[4 * i + 1] = make_float4(v0.w, v1.x, v1.y, 0.0f);
        g_points4[4 * i + 2] = make_float4(v1.z, v1.w, v2.x, 0.0f);
        g_points4[4 * i + 3] = make_float4(v2.y, v2.z, v2.w, 0.0f);
    }
    int rem_base = n_quads * 4;
    int r = rem_base + i;
    if (blockIdx.x == 0 && r < n_pts) {
        const float* p = points + (size_t)r * 3;
        g_points4[r] = make_float4(__ldg(p), __ldg(p + 1), __ldg(p + 2), 0.0f);
    }
}

__global__ __launch_bounds__(THREADS, 2) void residual_kernel(
    const float4* __restrict__ obs4,
    const float* __restrict__ K,
    const float* __restrict__ poses,
    const int4* __restrict__ cidx4,
    const int4* __restrict__ pidx4,
    const int* __restrict__ cidx,
    const int* __restrict__ pidx,
    const float2* __restrict__ obs2,
    float4* __restrict__ out4,
    float2* __restrict__ out2,
    int n_obs, int n_cam)
{
    extern __shared__ float4 psm[];   // [n_cam] a-rows then [n_cam] b-rows
    float4* pa_t = psm;               // tx ty tz qx
    float4* pb_t = psm + n_cam;       // qy qz qw pad

    const int tid = threadIdx.x;

    // Stage poses: 7 floats/cam -> split float4 tables.
    {
        float* a_f = (float*)pa_t;
        float* b_f = (float*)pb_t;
        const int n_pose_f = n_cam * 7;
        for (int idx = tid; idx < n_pose_f; idx += THREADS) {
            int c = idx / 7;
            int k = idx - c * 7;
            float v = __ldg(&poses[idx]);
            if (k < 4) a_f[c * 4 + k] = v;
            else       b_f[c * 4 + (k - 4)] = v;
        }
    }
    __syncthreads();

    const float fx = __ldg(&K[0]);
    const float cxx = __ldg(&K[2]);
    const float fy = __ldg(&K[4]);
    const float cyy = __ldg(&K[5]);

    const int n_quads = n_obs >> 2;
    const int gsz = gridDim.x * THREADS;

    int q = blockIdx.x * THREADS + tid;

    // ---- pipeline prologue: load indices + points for first iteration ----
    int4 c4, p4;
    float4 pt0, pt1, pt2, pt3;
    if (q < n_quads) {
        c4 = __ldg(&cidx4[q]);
        p4 = __ldg(&pidx4[q]);
        pt0 = __ldg(&g_points4[p4.x]);
        pt1 = __ldg(&g_points4[p4.y]);
        pt2 = __ldg(&g_points4[p4.z]);
        pt3 = __ldg(&g_points4[p4.w]);
    }

    while (q < n_quads) {
        const int qn = q + gsz;
        const bool has_next = (qn < n_quads);
        const int qs = has_next ? qn : q;  // safe index for prefetch

        // ---- prefetch next iteration: indices then dependent point gathers ----
        int4 c4n = __ldg(&cidx4[qs]);
        int4 p4n = __ldg(&pidx4[qs]);
        float4 n0 = __ldg(&g_points4[p4n.x]);
        float4 n1 = __ldg(&g_points4[p4n.y]);
        float4 n2 = __ldg(&g_points4[p4n.z]);
        float4 n3 = __ldg(&g_points4[p4n.w]);

        // ---- current iteration compute (overlaps with prefetch latency) ----
        float4 ob0 = __ldg(&obs4[2 * q]);
        float4 ob1 = __ldg(&obs4[2 * q + 1]);

        float4 ptc[4] = {pt0, pt1, pt2, pt3};
        int cis[4] = {c4.x, c4.y, c4.z, c4.w};
        float obx[4] = {ob0.x, ob0.z, ob1.x, ob1.z};
        float oby[4] = {ob0.y, ob0.w, ob1.y, ob1.w};
        float res[8];

        #pragma unroll
        for (int j = 0; j < 4; j++) {
            float4 a = pa_t[cis[j]];
            float4 b = pb_t[cis[j]];
            float tx = a.x, ty = a.y, tz = a.z;
            float qx = a.w, qy = b.x, qz = b.y, qw = b.z;
            float X = ptc[j].x, Y = ptc[j].y, Z = ptc[j].z;

            float uvx = qy * Z - qz * Y;
            float uvy = qz * X - qx * Z;
            float uvz = qx * Y - qy * X;
            float wx = fmaf(qw, X, uvx);
            float wy = fmaf(qw, Y, uvy);
            float wz = fmaf(qw, Z, uvz);
            float c2x = qy * wz - qz * wy;
            float c2y = qz * wx - qx * wz;
            float c2z = qx * wy - qy * wx;
            float Xc = fmaf(2.0f, c2x, X) + tx;
            float Yc = fmaf(2.0f, c2y, Y) + ty;
            float Zc = fmaf(2.0f, c2z, Z) + tz;

            float invz = __fdividef(1.0f, Zc);
            res[2 * j + 0] = fmaf(fx * Xc, invz, cxx) - obx[j];
            res[2 * j + 1] = fmaf(fy * Yc, invz, cyy) - oby[j];
        }

        out4[2 * q]     = make_float4(res[0], res[1], res[2], res[3]);
        out4[2 * q + 1] = make_float4(res[4], res[5], res[6], res[7]);

        // ---- rotate pipeline ----
        c4 = c4n;
        pt0 = n0; pt1 = n1; pt2 = n2; pt3 = n3;
        q = qn;
    }

    // ---- tail: n_obs % 4 leftovers (block 0 only) ----
    const int rem_base = n_quads << 2;
    if (blockIdx.x == 0) {
        for (int i = rem_base + tid; i < n_obs; i += THREADS) {
            int ci = __ldg(&cidx[i]);
            int pi = __ldg(&pidx[i]);
            float4 a = pa_t[ci];
            float4 b = pb_t[ci];
            float tx = a.x, ty = a.y, tz = a.z;
            float qx = a.w, qy = b.x, qz = b.y, qw = b.z;
            float4 p = __ldg(&g_points4[pi]);
            float X = p.x, Y = p.y, Z = p.z;

            float uvx = qy * Z - qz * Y;
            float uvy = qz * X - qx * Z;
            float uvz = qx * Y - qy * X;
            float wx = fmaf(qw, X, uvx);
            float wy = fmaf(qw, Y, uvy);
            float wz = fmaf(qw, Z, uvz);
            float c2x = qy * wz - qz * wy;
            float c2y = qz * wx - qx * wz;
            float c2z = qx * wy - qy * wx;
            float Xc = fmaf(2.0f, c2x, X) + tx;
            float Yc = fmaf(2.0f, c2y, Y) + ty;
            float Zc = fmaf(2.0f, c2z, Z) + tz;
            float invz = __fdividef(1.0f, Zc);
            float2 ob = __ldg(&obs2[i]);
            float2 r;
            r.x = fmaf(fx * Xc, invz, cxx) - ob.x;
            r.y = fmaf(fy * Yc, invz, cyy) - ob.y;
            out2[i] = r;
        }
    }
}

extern "C" void kernel_launch(void* const* d_in, const int* in_sizes, int n_in,
                              void* d_out, int out_size) {
    const float* observes = (const float*)d_in[0];
    const float* K        = (const float*)d_in[1];
    const float* poses    = (const float*)d_in[2];
    const float* points   = (const float*)d_in[3];
    const int* cidx       = (const int*)d_in[4];
    const int* pidx       = (const int*)d_in[5];

    int n_obs = in_sizes[0] / 2;
    int n_cam = in_sizes[2] / 7;
    int n_pts = in_sizes[3] / 3;
    if (n_pts > N_PTS_MAX) n_pts = N_PTS_MAX;

    int smem = n_cam * 2 * sizeof(float4);  // 64000 B for n_cam=2000

    cudaFuncSetAttribute(residual_kernel,
                         cudaFuncAttributeMaxDynamicSharedMemorySize, smem);

    int pq = n_pts / 4;
    int pblocks = (pq + 255) / 256;
    if (pblocks < 1) pblocks = 1;
    repack_points_kernel<<<pblocks, 256>>>((const float4*)points, points, pq, n_pts);

    int blocks = 148 * 2;  // 2 blocks/SM
    residual_kernel<<<blocks, THREADS, smem>>>(
        (const float4*)observes, K, poses,
        (const int4*)cidx, (const int4*)pidx,
        cidx, pidx, (const float2*)observes,
        (float4*)d_out, (float2*)d_out,
        n_obs, n_cam);
}